// round 15
// baseline (speedup 1.0000x reference)
#include <cuda_runtime.h>
#include <cuda_bf16.h>
#include <math_constants.h>
#include <cstdint>

#define NN 10000
#define EE 320000
#define HD 256      // heads*dim
#define QK 1024     // q|k|v|skip packed width

// ---------------- scratch (device globals; no allocation allowed) ----------------
__device__ float g_Whi1[256 * QK];    // W hi plane, [k][n] layout
__device__ float g_Wlo1[256 * QK];    // W lo plane (tf32-rounded)
__device__ float g_bp1[QK];
__device__ float g_Whi2[256 * QK];
__device__ float g_Wlo2[256 * QK];
__device__ float g_bp2[QK];
__device__ float g_Wqe1[256 * 8];
__device__ float g_bqe1[8];
__device__ float g_Wqe2[256 * 8];
__device__ float g_bqe2[8];
__device__ float g_Ahi[(size_t)NN * 256];   // x hi plane [m][k]
__device__ float g_Alo[(size_t)NN * 256];   // x lo plane (tf32-rounded)
__device__ float g_qkvs[(size_t)NN * QK];   // 40 MB
__device__ float g_h1[(size_t)NN * HD];
__device__ float g_h2[(size_t)NN * HD];
__device__ float g_qwe[NN * 8];
__device__ float2 g_dc[NN * 8];
__device__ float g_out[(size_t)NN * HD];
__device__ int   g_srcdst[2 * EE];
__device__ int   g_is64;
// CSR by dst
__device__ int   g_cnt[NN];
__device__ int   g_cur[NN];
__device__ int   g_off[NN + 1];
__device__ int   g_esrc[EE];
__device__ float g_eew[EE];

__device__ __forceinline__ float tf32_hi(float v) {
    uint32_t h;
    asm("cvt.rna.tf32.f32 %0, %1;" : "=r"(h) : "f"(v));
    return __uint_as_float(h);
}

// m16n8k8 tf32 mma (baseline sm_80+ PTX; tensor pipe on sm_103)
__device__ __forceinline__ void mma_tf32(float* c, const uint32_t* a, const uint32_t* b) {
    asm volatile(
        "mma.sync.aligned.m16n8k8.row.col.f32.tf32.tf32.f32 "
        "{%0,%1,%2,%3}, {%4,%5,%6,%7}, {%8,%9}, {%0,%1,%2,%3};"
        : "+f"(c[0]), "+f"(c[1]), "+f"(c[2]), "+f"(c[3])
        : "r"(a[0]), "r"(a[1]), "r"(a[2]), "r"(a[3]), "r"(b[0]), "r"(b[1]));
}

// ---------------- edge index dtype detect + convert ----------------
__global__ void detect_kernel(const void* ei) {
    if (blockIdx.x == 0 && threadIdx.x == 0) {
        const int* w = (const int*)ei;
        int all_zero = 1;
        for (int i = 0; i < 32; i++) {
            if (w[2 * i + 1] != 0) { all_zero = 0; break; }
        }
        g_is64 = all_zero;
    }
}

__global__ void convert_kernel(const void* ei) {
    int i = blockIdx.x * blockDim.x + threadIdx.x;
    if (i >= 2 * EE) return;
    if (g_is64)
        g_srcdst[i] = (int)((const long long*)ei)[i];
    else
        g_srcdst[i] = ((const int*)ei)[i];
}

// ---------------- CSR build ----------------
__global__ void zero_cnt(void) {
    int i = blockIdx.x * blockDim.x + threadIdx.x;
    if (i < NN) g_cnt[i] = 0;
}

__global__ void count_kernel(void) {
    int e = blockIdx.x * blockDim.x + threadIdx.x;
    if (e < EE) atomicAdd(&g_cnt[g_srcdst[EE + e]], 1);
}

__global__ void scan_kernel(void) {
    __shared__ int s[1024];
    int t = threadIdx.x;
    int base = t * 10;
    int local[10];
    int sum = 0;
#pragma unroll
    for (int i = 0; i < 10; i++) {
        int idx = base + i;
        int v = (idx < NN) ? g_cnt[idx] : 0;
        local[i] = v; sum += v;
    }
    s[t] = sum;
    __syncthreads();
    for (int off = 1; off < 1024; off <<= 1) {
        int v = (t >= off) ? s[t - off] : 0;
        __syncthreads();
        if (t >= off) s[t] += v;
        __syncthreads();
    }
    int excl = (t == 0) ? 0 : s[t - 1];
#pragma unroll
    for (int i = 0; i < 10; i++) {
        int idx = base + i;
        if (idx < NN) { g_off[idx] = excl; g_cur[idx] = 0; }
        excl += local[i];
    }
    if (t == 1023) g_off[NN] = s[1023];
}

__global__ void scatter_kernel(const float* __restrict__ ew) {
    int e = blockIdx.x * blockDim.x + threadIdx.x;
    if (e >= EE) return;
    int d = g_srcdst[EE + e];
    int pos = g_off[d] + atomicAdd(&g_cur[d], 1);
    g_esrc[pos] = g_srcdst[e];
    g_eew[pos] = ew[e];
}

// ---------------- weight packing: W hi/lo planes in [k][n] layout + bias + Wqe fold ----------------
__global__ void pack_kernel(const float* __restrict__ Wq, const float* __restrict__ bq,
                            const float* __restrict__ Wk, const float* __restrict__ bk,
                            const float* __restrict__ Wv, const float* __restrict__ bv,
                            const float* __restrict__ Ws, const float* __restrict__ bs,
                            const float* __restrict__ We,
                            float* __restrict__ Whi, float* __restrict__ Wlo,
                            float* __restrict__ bp,
                            float* __restrict__ Wqe, float* __restrict__ bqe) {
    int i = blockIdx.x * blockDim.x + threadIdx.x;
    if (i >= 256 * QK) return;
    int k = i >> 10, n = i & 1023;
    const float* W; const float* b; int cc;
    if (n < 256)      { W = Wq; b = bq; cc = n; }
    else if (n < 512) { W = Wk; b = bk; cc = n - 256; }
    else if (n < 768) { W = Wv; b = bv; cc = n - 512; }
    else              { W = Ws; b = bs; cc = n - 768; }
    float v = W[k * 256 + cc];
    float hf = tf32_hi(v);
    Whi[i] = hf;
    Wlo[i] = tf32_hi(v - hf);
    if (k == 0) bp[n] = b[cc];
    if (i < 2048) {
        int rr = i >> 3, h = i & 7;
        float s = 0.f;
#pragma unroll
        for (int t = 0; t < 32; t++) s += Wq[rr * 256 + h * 32 + t] * We[h * 32 + t];
        Wqe[rr * 8 + h] = s;
    }
    if (i < 8) {
        float s = 0.f;
#pragma unroll
        for (int t = 0; t < 32; t++) s += bq[i * 32 + t] * We[i * 32 + t];
        bqe[i] = s;
    }
}

// ---------------- layer-1 input split: x -> hi/lo tf32 planes ----------------
__global__ void split_kernel(const float* __restrict__ x) {
    int i = blockIdx.x * blockDim.x + threadIdx.x;
    if (i >= NN * 256) return;
    float v = x[i];
    float hf = tf32_hi(v);
    g_Ahi[i] = hf;
    g_Alo[i] = tf32_hi(v - hf);
}

// ---------------- per-node q.We ----------------
__global__ void qwe_kernel(const float* __restrict__ x, const float* __restrict__ Wqe,
                           const float* __restrict__ bqe) {
    int gt = blockIdx.x * blockDim.x + threadIdx.x;
    int node = gt >> 5, lane = gt & 31;
    if (node >= NN) return;
    float xv[8];
#pragma unroll
    for (int j = 0; j < 8; j++) xv[j] = x[(size_t)node * 256 + j * 32 + lane];
    float p[8];
#pragma unroll
    for (int h = 0; h < 8; h++) {
        float s = 0.f;
#pragma unroll
        for (int j = 0; j < 8; j++) s += xv[j] * Wqe[(j * 32 + lane) * 8 + h];
#pragma unroll
        for (int off = 16; off; off >>= 1) s += __shfl_xor_sync(0xffffffffu, s, off);
        p[h] = s;
    }
    if (lane < 8) g_qwe[node * 8 + lane] = p[lane] + bqe[lane];
}

// ---------------- mma.sync tf32 GEMM (3xTF32), fragment-major SMEM ----------------
// Block 128x128, BK=32, 8 warps (2x4), warp tile 64x32, m16n8k8 fragments.
// Ap[mt 0..7][ks 0..3][lane 0..31][reg 0..3]  (A fragment-major: one LDS.128/frag)
// Bp[nt 0..15][ks 0..3][lane 0..31][reg 0..1] (B fragment-major: one LDS.64/frag)

__global__ __launch_bounds__(256, 2)
void gemm_mma(const float* __restrict__ Whi, const float* __restrict__ Wlo,
              const float* __restrict__ bp, float* __restrict__ C) {
    __shared__ float Ap[8 * 4 * 32 * 4];   // 4096 floats = 16 KB
    __shared__ float Bp[16 * 4 * 32 * 2];  // 4096 floats = 16 KB

    int tid = threadIdx.x;
    int wid = tid >> 5, lane = tid & 31;
    int warpM = (wid & 1) * 64;    // 2 warps over M (4 m16 tiles each)
    int warpN = (wid >> 1) * 32;   // 4 warps over N (4 n8 tiles each)
    int mtBase = warpM >> 4;       // first m16 tile index
    int ntBase = warpN >> 3;       // first n8 tile index
    int rowBase = blockIdx.y * 128, colBase = blockIdx.x * 128;
    int lq = lane & 3, lg = lane >> 2;

    float acc[4][4][4];
#pragma unroll
    for (int mt = 0; mt < 4; mt++)
#pragma unroll
        for (int nt = 0; nt < 4; nt++)
#pragma unroll
            for (int r = 0; r < 4; r++) acc[mt][nt][r] = 0.f;

    const float* Apl[3] = { g_Ahi, g_Alo, g_Ahi };
    const float* Bpl[3] = { Whi, Whi, Wlo };

    for (int p = 0; p < 3; p++) {
        const float* Aglob = Apl[p];
        const float* Bglob = Bpl[p];
        for (int c = 0; c < 8; c++) {
            int k0 = c * 32;
            // A copy-in: 128 rows x 8 float4 = 1024 float4; permuted fragment-major store
#pragma unroll
            for (int it = 0; it < 4; it++) {
                int idx = tid + it * 256;
                int m = idx >> 3, q = idx & 7;      // q: float4 group in k (kc = q*4)
                int arow = rowBase + m;
                float4 v = make_float4(0.f, 0.f, 0.f, 0.f);
                if (arow < NN) v = *(const float4*)(Aglob + (size_t)arow * 256 + k0 + q * 4);
                int mt = m >> 4, r = m & 15;
                int ks = q >> 1;
                int reg = (r >> 3) + 2 * (q & 1);   // (kk0>>2) = q&1
                float* dst = Ap + (((mt * 4 + ks) * 32) + (r & 7) * 4) * 4 + reg;
                dst[0]  = v.x;   // lane offset j adds j*4 floats
                dst[4]  = v.y;
                dst[8]  = v.z;
                dst[12] = v.w;
            }
            // B copy-in: 32 k-rows x 32 float4 = 1024 float4; permuted fragment-major store
#pragma unroll
            for (int it = 0; it < 4; it++) {
                int idx = tid + it * 256;
                int k = idx >> 5, n4 = idx & 31;
                float4 v = *(const float4*)(Bglob + (size_t)(k0 + k) * QK + colBase + n4 * 4);
                int ks = k >> 3, kk = k & 7;
                int reg = kk >> 2;
                int n0 = n4 * 4;
                float fv[4] = { v.x, v.y, v.z, v.w };
#pragma unroll
                for (int j = 0; j < 4; j++) {
                    int n = n0 + j;
                    int nt = n >> 3, nl = n & 7;
                    Bp[(((nt * 4 + ks) * 32) + nl * 4 + (kk & 3)) * 2 + reg] = fv[j];
                }
            }
            __syncthreads();
#pragma unroll
            for (int ks = 0; ks < 4; ks++) {
                uint32_t af[4][4], bf[4][2];
#pragma unroll
                for (int mt = 0; mt < 4; mt++) {
                    float4 av = *(const float4*)(Ap + (((mtBase + mt) * 4 + ks) * 32 + lane) * 4);
                    af[mt][0] = __float_as_uint(av.x);
                    af[mt][1] = __float_as_uint(av.y);
                    af[mt][2] = __float_as_uint(av.z);
                    af[mt][3] = __float_as_uint(av.w);
                }
#pragma unroll
                for (int nt = 0; nt < 4; nt++) {
                    float2 bv = *(const float2*)(Bp + (((ntBase + nt) * 4 + ks) * 32 + lane) * 2);
                    bf[nt][0] = __float_as_uint(bv.x);
                    bf[nt][1] = __float_as_uint(bv.y);
                }
#pragma unroll
                for (int mt = 0; mt < 4; mt++)
#pragma unroll
                    for (int nt = 0; nt < 4; nt++)
                        mma_tf32(acc[mt][nt], af[mt], bf[nt]);
            }
            __syncthreads();
        }
    }

    // epilogue: bias + store. c0/c1: (row, col..col+1); c2/c3: (row+8, ...)
#pragma unroll
    for (int mt = 0; mt < 4; mt++) {
        int row = rowBase + warpM + mt * 16 + lg;
#pragma unroll
        for (int nt = 0; nt < 4; nt++) {
            int col = colBase + warpN + nt * 8 + 2 * lq;
            float2 bb = *(const float2*)(bp + col);
            if (row < NN) {
                float2 o0 = make_float2(acc[mt][nt][0] + bb.x, acc[mt][nt][1] + bb.y);
                *(float2*)(C + (size_t)row * QK + col) = o0;
            }
            if (row + 8 < NN) {
                float2 o1 = make_float2(acc[mt][nt][2] + bb.x, acc[mt][nt][3] + bb.y);
                *(float2*)(C + (size_t)(row + 8) * QK + col) = o1;
            }
        }
    }
}

// ---------------- CSR gather attention: one warp per (node, head), no atomics ----------------
__global__ __launch_bounds__(256)
void agg_kernel(const float* __restrict__ qwe) {
    int warpId = (blockIdx.x * blockDim.x + threadIdx.x) >> 5;
    int lane = threadIdx.x & 31;
    if (warpId >= NN * 8) return;
    int node = warpId >> 3, h = warpId & 7;
    float q = g_qkvs[(size_t)node * QK + h * 32 + lane];
    float qw = qwe[node * 8 + h];
    int beg = g_off[node], end = g_off[node + 1];

    float acc = 0.f, denom = 0.f, coeff = 0.f;

    float w0 = 0.f, k0 = 0.f, v0 = 0.f;
    float w1 = 0.f, k1 = 0.f, v1 = 0.f;
    if (beg < end) {
        int s = g_esrc[beg]; w0 = g_eew[beg];
        k0 = g_qkvs[(size_t)s * QK + 256 + h * 32 + lane];
        v0 = g_qkvs[(size_t)s * QK + 512 + h * 32 + lane];
    }
    if (beg + 1 < end) {
        int s = g_esrc[beg + 1]; w1 = g_eew[beg + 1];
        k1 = g_qkvs[(size_t)s * QK + 256 + h * 32 + lane];
        v1 = g_qkvs[(size_t)s * QK + 512 + h * 32 + lane];
    }
    for (int i = beg; i < end; i++) {
        float w2 = 0.f, k2 = 0.f, v2 = 0.f;
        if (i + 2 < end) {
            int s = g_esrc[i + 2]; w2 = g_eew[i + 2];
            k2 = g_qkvs[(size_t)s * QK + 256 + h * 32 + lane];
            v2 = g_qkvs[(size_t)s * QK + 512 + h * 32 + lane];
        }
        float dv = q * k0;
#pragma unroll
        for (int off = 16; off; off >>= 1)
            dv += __shfl_xor_sync(0xffffffffu, dv, off);
        float ex = __expf((dv + w0 * qw) * 0.17677669529663687f);
        denom += ex;
        coeff += ex * w0;
        acc += ex * v0;
        w0 = w1; k0 = k1; v0 = v1;
        w1 = w2; k1 = k2; v1 = v2;
    }
    g_out[(size_t)node * HD + h * 32 + lane] = acc;
    if (lane == 0) g_dc[node * 8 + h] = make_float2(denom, coeff);
}

// ---------------- finalize: normalize (+ coeff*We), gated skip; fused hi/lo split ----------------
__global__ void finalize(const float* __restrict__ Wb, const float* __restrict__ We,
                         float* __restrict__ hout, int do_split) {
    int gt = blockIdx.x * blockDim.x + threadIdx.x;
    int node = gt >> 5;
    int lane = gt & 31;
    if (node >= NN) return;
    const float* xr = g_qkvs + (size_t)node * QK + 768;
    const float* oa = g_out + (size_t)node * HD;
    float o[8], x[8];
    float dot = 0.f;
#pragma unroll
    for (int j = 0; j < 8; j++) {
        int c = j * 32 + lane;
        float2 dc = g_dc[node * 8 + j];
        float ov = (oa[c] + dc.y * We[c]) / (dc.x + 1e-16f);
        float xv = xr[c];
        o[j] = ov; x[j] = xv;
        dot += ov * Wb[c] + xv * Wb[256 + c] + (ov - xv) * Wb[512 + c];
    }
#pragma unroll
    for (int off = 16; off; off >>= 1)
        dot += __shfl_xor_sync(0xffffffffu, dot, off);
    float beta = 1.f / (1.f + __expf(-dot));
#pragma unroll
    for (int j = 0; j < 8; j++) {
        size_t idx = (size_t)node * HD + j * 32 + lane;
        float hv = beta * x[j] + (1.f - beta) * o[j];
        hout[idx] = hv;
        if (do_split) {
            float hf = tf32_hi(hv);
            g_Ahi[idx] = hf;
            g_Alo[idx] = tf32_hi(hv - hf);
        }
    }
}

// ---------------- host orchestration ----------------
static void run_layer(const float* xin, const float* Whi, const float* Wlo,
                      const float* bp, const float* Wqe, const float* bqe,
                      const float* We, const float* Wb, float* hout, int do_split) {
    float* qkvs; cudaGetSymbolAddress((void**)&qkvs, g_qkvs);
    float* qwe;  cudaGetSymbolAddress((void**)&qwe, g_qwe);
    dim3 gg(QK / 128, (NN + 127) / 128);
    gemm_mma<<<gg, 256>>>(Whi, Wlo, bp, qkvs);
    qwe_kernel<<<(NN * 32 + 255) / 256, 256>>>(xin, Wqe, bqe);
    agg_kernel<<<(NN * 8 * 32 + 255) / 256, 256>>>(qwe);
    finalize<<<(NN * 32 + 127) / 128, 128>>>(Wb, We, hout, do_split);
}

extern "C" void kernel_launch(void* const* d_in, const int* in_sizes, int n_in,
                              void* d_out, int out_size) {
    const float* x  = (const float*)d_in[0];
    const void*  ei = d_in[1];
    const float* ew = (const float*)d_in[2];
    const float* Wq1 = (const float*)d_in[3];  const float* bq1 = (const float*)d_in[4];
    const float* Wk1 = (const float*)d_in[5];  const float* bk1 = (const float*)d_in[6];
    const float* Wv1 = (const float*)d_in[7];  const float* bv1 = (const float*)d_in[8];
    const float* We1 = (const float*)d_in[9];
    const float* Ws1 = (const float*)d_in[10]; const float* bs1 = (const float*)d_in[11];
    const float* Wb1 = (const float*)d_in[12];
    const float* Wq2 = (const float*)d_in[13]; const float* bq2 = (const float*)d_in[14];
    const float* Wk2 = (const float*)d_in[15]; const float* bk2 = (const float*)d_in[16];
    const float* Wv2 = (const float*)d_in[17]; const float* bv2 = (const float*)d_in[18];
    const float* We2 = (const float*)d_in[19];
    const float* Ws2 = (const float*)d_in[20]; const float* bs2 = (const float*)d_in[21];
    const float* Wb2 = (const float*)d_in[22];

    float *Whi1, *Wlo1, *bp1, *Whi2, *Wlo2, *bp2;
    float *Wqe1, *bqe1, *Wqe2, *bqe2, *h1, *h2;
    cudaGetSymbolAddress((void**)&Whi1, g_Whi1);
    cudaGetSymbolAddress((void**)&Wlo1, g_Wlo1);
    cudaGetSymbolAddress((void**)&bp1, g_bp1);
    cudaGetSymbolAddress((void**)&Whi2, g_Whi2);
    cudaGetSymbolAddress((void**)&Wlo2, g_Wlo2);
    cudaGetSymbolAddress((void**)&bp2, g_bp2);
    cudaGetSymbolAddress((void**)&Wqe1, g_Wqe1);
    cudaGetSymbolAddress((void**)&bqe1, g_bqe1);
    cudaGetSymbolAddress((void**)&Wqe2, g_Wqe2);
    cudaGetSymbolAddress((void**)&bqe2, g_bqe2);
    cudaGetSymbolAddress((void**)&h1, g_h1);
    cudaGetSymbolAddress((void**)&h2, g_h2);

    // launches 0-2: packing + layer-1 input split
    pack_kernel<<<(256 * QK + 255) / 256, 256>>>(Wq1, bq1, Wk1, bk1, Wv1, bv1, Ws1, bs1,
                                                 We1, Whi1, Wlo1, bp1, Wqe1, bqe1);
    pack_kernel<<<(256 * QK + 255) / 256, 256>>>(Wq2, bq2, Wk2, bk2, Wv2, bv2, Ws2, bs2,
                                                 We2, Whi2, Wlo2, bp2, Wqe2, bqe2);
    split_kernel<<<(NN * 256 + 255) / 256, 256>>>(x);

    // launch 3: layer-1 GEMM (ncu-captured slot)
    float* qkvs; cudaGetSymbolAddress((void**)&qkvs, g_qkvs);
    float* qwe;  cudaGetSymbolAddress((void**)&qwe, g_qwe);
    {
        dim3 gg(QK / 128, (NN + 127) / 128);
        gemm_mma<<<gg, 256>>>(Whi1, Wlo1, bp1, qkvs);
    }
    qwe_kernel<<<(NN * 32 + 255) / 256, 256>>>(x, Wqe1, bqe1);

    // CSR build (needed only by agg)
    detect_kernel<<<1, 32>>>(ei);
    convert_kernel<<<(2 * EE + 255) / 256, 256>>>(ei);
    zero_cnt<<<(NN + 255) / 256, 256>>>();
    count_kernel<<<(EE + 255) / 256, 256>>>();
    scan_kernel<<<1, 1024>>>();
    scatter_kernel<<<(EE + 255) / 256, 256>>>(ew);

    // layer 1 tail
    agg_kernel<<<(NN * 8 * 32 + 255) / 256, 256>>>(qwe);
    finalize<<<(NN * 32 + 127) / 128, 128>>>(Wb1, We1, h1, 1);

    // layers 2, 3
    run_layer(h1, Whi2, Wlo2, bp2, Wqe2, bqe2, We2, Wb2, h2, 1);
    run_layer(h2, Whi2, Wlo2, bp2, Wqe2, bqe2, We2, Wb2, (float*)d_out, 0);
}